// round 8
// baseline (speedup 1.0000x reference)
#include <cuda_runtime.h>
#include <cstdint>

// ============================================================
// BinarizeConv2d: out = conv3x3(sign(x), sign(mix(W))) * scale * alpha
// Implicit GEMM, mma.sync m16n8k32 s8s8s32 (exact for ±1), sm_100.
// R8: CTA tile 128M x 256N, warp tile 64x64 (8 warps) -> 128B smem/MMA
//     (was 192B); 2-stage x 48KB cp.async, 2 CTAs/SM; coalesced prep_w.
// ============================================================

#define B_   32
#define CIN  256
#define COUT 256
#define H_   56
#define W_   56
#define HP   58
#define WP   58
#define HW   3136      // 56*56

// int8 encodings of {+1,-1,0}: 0x01, 0xFF, 0x00
__device__ uint8_t g_xb[(size_t)B_ * HP * WP * CIN];  // sign(x), NHWC padded (borders stay 0)
__device__ uint8_t g_wb[9 * COUT * CIN];              // sign(real_w) [tap][co][ci]
__device__ float   g_sa[COUT];                        // alpha * scale

// ---------------- PTX helpers ----------------
__device__ __forceinline__ uint32_t smem_u32(const void* p) {
    uint32_t a;
    asm("{ .reg .u64 t; cvta.to.shared.u64 t, %1; cvt.u32.u64 %0, t; }" : "=r"(a) : "l"(p));
    return a;
}
#define CP16(d, s)   asm volatile("cp.async.cg.shared.global [%0], [%1], 16;" :: "r"(d), "l"(s) : "memory")
#define CP_COMMIT()  asm volatile("cp.async.commit_group;" ::: "memory")
#define CP_WAIT(n)   asm volatile("cp.async.wait_group %0;" :: "n"(n) : "memory")

#define LDSM4(r, a)                                                          \
    asm volatile("ldmatrix.sync.aligned.m8n8.x4.shared.b16 {%0,%1,%2,%3}, [%4];" \
        : "=r"((r)[0]), "=r"((r)[1]), "=r"((r)[2]), "=r"((r)[3]) : "r"(a))

#define MMAI(d, a, b0, b1)                                                   \
    asm volatile("mma.sync.aligned.m16n8k32.row.col.s32.s8.s8.s32 "          \
        "{%0,%1,%2,%3}, {%4,%5,%6,%7}, {%8,%9}, {%0,%1,%2,%3};"              \
        : "+r"((d)[0]), "+r"((d)[1]), "+r"((d)[2]), "+r"((d)[3])             \
        : "r"((a)[0]), "r"((a)[1]), "r"((a)[2]), "r"((a)[3]),                \
          "r"(b0), "r"(b1))

__device__ __forceinline__ uint8_t sign_s8(float v) {
    return (v > 0.f) ? 0x01 : ((v < 0.f) ? 0xFF : 0x00);
}

// ---------------- merged prep kernel ----------------
// blocks [0,256):          weight mix/sign/scale  (co = blockIdx.x), smem-staged
// blocks [256,256+7168):   binarize x, NCHW -> padded NHWC int8
__global__ void prep_all(const float* __restrict__ Wt, const float* __restrict__ RV,
                         const float* __restrict__ alpha, const float* __restrict__ x) {
    const int tid = threadIdx.x;
    if (blockIdx.x < COUT) {
        const int co = blockIdx.x, ci = tid;
        __shared__ float ws[4 * 2304];   // [k][ci*9+t], 36KB
        __shared__ float red[256];
        const size_t ks = (size_t)COUT * CIN * 9;
        // coalesced staging: 4 contiguous 2304-float slices
#pragma unroll
        for (int u = 0; u < 9; u++) {
            int idx = tid + 256 * u;                 // 0..2303
            const float* src = Wt + (size_t)co * 2304 + idx;
            ws[idx]        = src[0];
            ws[idx + 2304] = src[ks];
            ws[idx + 4608] = src[2 * ks];
            ws[idx + 6912] = src[3 * ks];
        }
        __syncthreads();
        const float r0 = RV[0], r1 = RV[1], r2 = RV[2], r3 = RV[3];
        float acc = 0.f;
#pragma unroll
        for (int t = 0; t < 9; t++) {
            int idx = ci * 9 + t;
            float rw = r0 * ws[idx] + r1 * ws[idx + 2304] +
                       r2 * ws[idx + 4608] + r3 * ws[idx + 6912];
            acc += fabsf(rw);
            g_wb[((size_t)t * COUT + co) * CIN + ci] = sign_s8(rw);
        }
        red[ci] = acc;
        __syncthreads();
        for (int st = 128; st > 0; st >>= 1) {
            if (ci < st) red[ci] += red[ci + st];
            __syncthreads();
        }
        if (ci == 0) g_sa[co] = alpha[co] * (red[0] * (1.0f / 2304.0f));
    } else {
        const int id = blockIdx.x - COUT;
        const int cc = id & 3;             // 64-ci chunk
        const int h  = (id >> 2) % H_;
        const int b  = (id >> 2) / H_;
        __shared__ __align__(16) uint8_t sb[56 * 64];  // [w][ci]
        const float* xp = x + (((size_t)b * CIN + cc * 64) * H_ + h) * W_;
        // float4 loads: 64 ci x 14 float4 = 896
        for (int i = tid; i < 896; i += 256) {
            int ci = i / 14, w4 = (i - ci * 14) * 4;
            float4 v = *reinterpret_cast<const float4*>(xp + (size_t)ci * HW + w4);
            sb[(w4 + 0) * 64 + ci] = sign_s8(v.x);
            sb[(w4 + 1) * 64 + ci] = sign_s8(v.y);
            sb[(w4 + 2) * 64 + ci] = sign_s8(v.z);
            sb[(w4 + 3) * 64 + ci] = sign_s8(v.w);
        }
        __syncthreads();
        uint8_t* dst0 = g_xb + (((size_t)b * HP + (h + 1)) * WP + 1) * CIN + cc * 64;
        for (int u = tid; u < 224; u += 256) {     // 56 w x 4 x 16B
            int w = u >> 2, s16 = (u & 3) * 16;
            *reinterpret_cast<uint4*>(dst0 + (size_t)w * CIN + s16) =
                *reinterpret_cast<const uint4*>(sb + w * 64 + s16);
        }
    }
}

// ---------------- main GEMM kernel ----------------
#define NSTG     2
#define A_BYTES  16384                 // 128 M-rows x 128B
#define B_BYTES  32768                 // 256 N-rows x 128B
#define STG      49152                 // A + B
#define GSMEM    (NSTG * STG)          // 98304 B -> 2 CTAs/SM
#define NCHUNK   18                    // 9 taps x 2 ci-chunks of 128

__global__ void __launch_bounds__(256, 2) bconv_gemm(float* __restrict__ out) {
    extern __shared__ char smem[];
    const uint32_t sbase = smem_u32(smem);
    const int tid  = threadIdx.x;
    const int warp = tid >> 5, lane = tid & 31;
    const int wm = warp >> 2;          // 0..1: M rows 64*wm..+63
    const int wn = warp & 3;           // 0..3: N cols 64*wn..+63
    const int m0 = blockIdx.x << 7;    // 784 tiles exact

    const int seg = tid & 7;   // 16B segment within 128B k-row
    const int rb  = tid >> 3;  // base row 0..31

    // ---- hoisted load addressing ----
    int aoff[4];
#pragma unroll
    for (int k = 0; k < 4; k++) {
        int m = m0 + rb + 32 * k;
        int ib  = m / HW;
        int rem = m - ib * HW;
        int h = rem / W_, w = rem - h * W_;
        aoff[k] = ((ib * HP + h) * WP + w) * CIN + seg * 16;
    }
    int boff[8];
#pragma unroll
    for (int k = 0; k < 8; k++) boff[k] = (rb + 32 * k) * CIN + seg * 16;
    const uint32_t dstb = rb * 128 + ((seg * 16) ^ ((rb & 7) << 4));

    const int rlo   = lane & 15;
    const int khalf = (lane >> 4) << 4;
    const int swz   = (rlo & 7) << 4;

    int d[4][8][4];
#pragma unroll
    for (int mi = 0; mi < 4; mi++)
#pragma unroll
        for (int ni = 0; ni < 8; ni++)
#pragma unroll
            for (int j = 0; j < 4; j++) d[mi][ni][j] = 0;

    auto load_chunk = [&](int chunk, int stage) {
        const int t  = chunk >> 1;                 // tap 0..8
        const int cc = (chunk & 1) << 7;           // ci base (0 or 128)
        const int kh = t / 3, kw = t - kh * 3;
        const int toffA = (kh * WP + kw) * CIN + cc;
        const int toffB = t * (COUT * CIN) + cc;
        const uint32_t stgA = sbase + stage * STG + dstb;
        const uint32_t stgB = stgA + A_BYTES;
#pragma unroll
        for (int k = 0; k < 4; k++)
            CP16(stgA + k * 4096, (const char*)g_xb + aoff[k] + toffA);
#pragma unroll
        for (int k = 0; k < 8; k++)
            CP16(stgB + k * 4096, (const char*)g_wb + boff[k] + toffB);
    };

    load_chunk(0, 0); CP_COMMIT();

    const int rowA0 = 64 * wm + rlo;
    const int rowB0 = 64 * wn + rlo;

    for (int i = 0; i < NCHUNK; i++) {
        CP_WAIT(0);                    // chunk i resident
        __syncthreads();               // visible to all warps; prev stage free
        if (i + 1 < NCHUNK) { load_chunk(i + 1, (i + 1) & 1); CP_COMMIT(); }

        const uint32_t stgA = sbase + (i & 1) * STG;
        const uint32_t stgB = stgA + A_BYTES;
#pragma unroll
        for (int ks = 0; ks < 4; ks++) {
            const int kb = ks * 32 + khalf;
            uint32_t a[4][4], bf[4][4];
#pragma unroll
            for (int mi2 = 0; mi2 < 4; mi2++)
                LDSM4(a[mi2], stgA + (rowA0 + 16 * mi2) * 128 + (kb ^ swz));
#pragma unroll
            for (int nj = 0; nj < 4; nj++)
                LDSM4(bf[nj], stgB + (rowB0 + 16 * nj) * 128 + (kb ^ swz));
#pragma unroll
            for (int nj = 0; nj < 4; nj++) {
#pragma unroll
                for (int mi2 = 0; mi2 < 4; mi2++) {
                    MMAI(d[mi2][2 * nj],     a[mi2], bf[nj][0], bf[nj][2]);
                    MMAI(d[mi2][2 * nj + 1], a[mi2], bf[nj][1], bf[nj][3]);
                }
            }
        }
        __syncthreads();               // all warps done reading stage i&1
    }

    // ---------------- epilogue ----------------
    int*  buf    = (int*)smem;                     // 64 cl x 128 rows = 32KB
    int*  stable = (int*)(smem + 40960);           // 128-entry row -> out offset (co=0)
    if (tid < 128) {
        int m = m0 + tid;
        int ib  = m / HW;
        int rem = m - ib * HW;
        stable[tid] = ib * (COUT * HW) + rem;      // + co*HW gives final offset
    }
    const int q  = lane & 3;
    const int rr = lane >> 2;
#pragma unroll 1
    for (int hh = 0; hh < 4; hh++) {               // co quarters of 64
        if (wn == hh) {
#pragma unroll
            for (int mi = 0; mi < 4; mi++)
#pragma unroll
                for (int ni = 0; ni < 8; ni++) {
                    int cl  = 8 * ni + 2 * q;
                    int row = 64 * wm + 16 * mi + rr;
                    buf[cl * 128 + row]           = d[mi][ni][0];
                    buf[(cl + 1) * 128 + row]     = d[mi][ni][1];
                    buf[cl * 128 + row + 8]       = d[mi][ni][2];
                    buf[(cl + 1) * 128 + row + 8] = d[mi][ni][3];
                }
        }
        __syncthreads();
#pragma unroll 4
        for (int it = 0; it < 32; it++) {
            int u  = tid + 256 * it;               // 0..8191
            int cl = u >> 7;
            int r  = u & 127;
            int co = hh * 64 + cl;
            out[stable[r] + co * HW] = (float)buf[cl * 128 + r] * __ldg(&g_sa[co]);
        }
        __syncthreads();
    }
}

// ---------------- launch ----------------
extern "C" void kernel_launch(void* const* d_in, const int* in_sizes, int n_in,
                              void* d_out, int out_size) {
    const float* x     = (const float*)d_in[0];  // [32,256,56,56]
    const float* wts   = (const float*)d_in[1];  // [4,256,256,3,3]
    const float* rv    = (const float*)d_in[2];  // [5]
    const float* alpha = (const float*)d_in[3];  // [256]
    float* out = (float*)d_out;

    cudaFuncSetAttribute(bconv_gemm, cudaFuncAttributeMaxDynamicSharedMemorySize, GSMEM);

    prep_all<<<COUT + 4 * H_ * B_, 256>>>(wts, rv, alpha, x);
    bconv_gemm<<<784, 256, GSMEM>>>(out);
}

// round 9
// speedup vs baseline: 2.6335x; 2.6335x over previous
#include <cuda_runtime.h>
#include <cstdint>

// ============================================================
// BinarizeConv2d: out = conv3x3(sign(x), sign(mix(W))) * scale * alpha
// Implicit GEMM, mma.sync m16n8k32 s8s8s32 (exact for ±1), sm_100.
// R9 = R7 champion (32Mx64N warp tile, 2 CTAs/SM, 3-stage cp.async)
//      + register-level fragment software pipelining (LDSM ahead of MMA)
//      + R8's coalesced prep.  (R8's 64x64 tile spilled: 128-reg cap.)
// ============================================================

#define B_   32
#define CIN  256
#define COUT 256
#define H_   56
#define W_   56
#define HP   58
#define WP   58
#define HW   3136      // 56*56

// int8 encodings of {+1,-1,0}: 0x01, 0xFF, 0x00
__device__ uint8_t g_xb[(size_t)B_ * HP * WP * CIN];  // sign(x), NHWC padded (borders stay 0)
__device__ uint8_t g_wb[9 * COUT * CIN];              // sign(real_w) [tap][co][ci]
__device__ float   g_sa[COUT];                        // alpha * scale

// ---------------- PTX helpers ----------------
__device__ __forceinline__ uint32_t smem_u32(const void* p) {
    uint32_t a;
    asm("{ .reg .u64 t; cvta.to.shared.u64 t, %1; cvt.u32.u64 %0, t; }" : "=r"(a) : "l"(p));
    return a;
}
#define CP16(d, s)   asm volatile("cp.async.cg.shared.global [%0], [%1], 16;" :: "r"(d), "l"(s) : "memory")
#define CP_COMMIT()  asm volatile("cp.async.commit_group;" ::: "memory")
#define CP_WAIT(n)   asm volatile("cp.async.wait_group %0;" :: "n"(n) : "memory")

#define LDSM4(r, a)                                                          \
    asm volatile("ldmatrix.sync.aligned.m8n8.x4.shared.b16 {%0,%1,%2,%3}, [%4];" \
        : "=r"((r)[0]), "=r"((r)[1]), "=r"((r)[2]), "=r"((r)[3]) : "r"(a))

#define MMAI(d, a, b0, b1)                                                   \
    asm volatile("mma.sync.aligned.m16n8k32.row.col.s32.s8.s8.s32 "          \
        "{%0,%1,%2,%3}, {%4,%5,%6,%7}, {%8,%9}, {%0,%1,%2,%3};"              \
        : "+r"((d)[0]), "+r"((d)[1]), "+r"((d)[2]), "+r"((d)[3])             \
        : "r"((a)[0]), "r"((a)[1]), "r"((a)[2]), "r"((a)[3]),                \
          "r"(b0), "r"(b1))

__device__ __forceinline__ uint8_t sign_s8(float v) {
    return (v > 0.f) ? 0x01 : ((v < 0.f) ? 0xFF : 0x00);
}

// ---------------- merged prep kernel (R8 version: coalesced) ----------------
__global__ void prep_all(const float* __restrict__ Wt, const float* __restrict__ RV,
                         const float* __restrict__ alpha, const float* __restrict__ x) {
    const int tid = threadIdx.x;
    if (blockIdx.x < COUT) {
        const int co = blockIdx.x, ci = tid;
        __shared__ float ws[4 * 2304];   // 36KB
        __shared__ float red[256];
        const size_t ks = (size_t)COUT * CIN * 9;
#pragma unroll
        for (int u = 0; u < 9; u++) {
            int idx = tid + 256 * u;                 // 0..2303
            const float* src = Wt + (size_t)co * 2304 + idx;
            ws[idx]        = src[0];
            ws[idx + 2304] = src[ks];
            ws[idx + 4608] = src[2 * ks];
            ws[idx + 6912] = src[3 * ks];
        }
        __syncthreads();
        const float r0 = RV[0], r1 = RV[1], r2 = RV[2], r3 = RV[3];
        float acc = 0.f;
#pragma unroll
        for (int t = 0; t < 9; t++) {
            int idx = ci * 9 + t;
            float rw = r0 * ws[idx] + r1 * ws[idx + 2304] +
                       r2 * ws[idx + 4608] + r3 * ws[idx + 6912];
            acc += fabsf(rw);
            g_wb[((size_t)t * COUT + co) * CIN + ci] = sign_s8(rw);
        }
        red[ci] = acc;
        __syncthreads();
        for (int st = 128; st > 0; st >>= 1) {
            if (ci < st) red[ci] += red[ci + st];
            __syncthreads();
        }
        if (ci == 0) g_sa[co] = alpha[co] * (red[0] * (1.0f / 2304.0f));
    } else {
        const int id = blockIdx.x - COUT;
        const int cc = id & 3;             // 64-ci chunk
        const int h  = (id >> 2) % H_;
        const int b  = (id >> 2) / H_;
        __shared__ __align__(16) uint8_t sb[56 * 64];  // [w][ci]
        const float* xp = x + (((size_t)b * CIN + cc * 64) * H_ + h) * W_;
        for (int i = tid; i < 896; i += 256) {     // 64 ci x 14 float4
            int ci = i / 14, w4 = (i - ci * 14) * 4;
            float4 v = *reinterpret_cast<const float4*>(xp + (size_t)ci * HW + w4);
            sb[(w4 + 0) * 64 + ci] = sign_s8(v.x);
            sb[(w4 + 1) * 64 + ci] = sign_s8(v.y);
            sb[(w4 + 2) * 64 + ci] = sign_s8(v.z);
            sb[(w4 + 3) * 64 + ci] = sign_s8(v.w);
        }
        __syncthreads();
        uint8_t* dst0 = g_xb + (((size_t)b * HP + (h + 1)) * WP + 1) * CIN + cc * 64;
        for (int u = tid; u < 224; u += 256) {
            int w = u >> 2, s16 = (u & 3) * 16;
            *reinterpret_cast<uint4*>(dst0 + (size_t)w * CIN + s16) =
                *reinterpret_cast<const uint4*>(sb + w * 64 + s16);
        }
    }
}

// ---------------- main GEMM kernel ----------------
#define NSTG     3
#define A_BYTES  16384                 // 128 M-rows x 128B
#define STG      32768                 // A(16K) + B(16K)
#define GSMEM    (NSTG * STG)          // 98304 B -> 2 CTAs/SM
#define NCHUNK   18                    // 9 taps x 2 ci-chunks of 128

__global__ void __launch_bounds__(256, 2) bconv_gemm(float* __restrict__ out) {
    extern __shared__ char smem[];
    const uint32_t sbase = smem_u32(smem);
    const int tid  = threadIdx.x;
    const int warp = tid >> 5, lane = tid & 31;
    const int mw = warp >> 1;          // 0..3: M rows 32*mw..+31
    const int nw = warp & 1;           // 0..1: N cols 64*nw..+63
    const int bidx = blockIdx.x;
    const int co0  = (bidx & 1) * 128;
    const int m0   = (bidx >> 1) << 7;   // 784*128 = 100352 exact

    const int seg = tid & 7;
    const int rb  = tid >> 3;

    int aoff[4];
#pragma unroll
    for (int k = 0; k < 4; k++) {
        int m = m0 + rb + 32 * k;
        int ib  = m / HW;
        int rem = m - ib * HW;
        int h = rem / W_, w = rem - h * W_;
        aoff[k] = ((ib * HP + h) * WP + w) * CIN + seg * 16;
    }
    int boff[4];
#pragma unroll
    for (int k = 0; k < 4; k++) boff[k] = (co0 + rb + 32 * k) * CIN + seg * 16;
    const uint32_t dstb = rb * 128 + ((seg * 16) ^ ((rb & 7) << 4));

    const int rlo   = lane & 15;
    const int khalf = (lane >> 4) << 4;
    const int swz   = (rlo & 7) << 4;

    int d[2][8][4];
#pragma unroll
    for (int mi = 0; mi < 2; mi++)
#pragma unroll
        for (int ni = 0; ni < 8; ni++)
#pragma unroll
            for (int j = 0; j < 4; j++) d[mi][ni][j] = 0;

    auto load_chunk = [&](int chunk, int stage) {
        const int t  = chunk >> 1;
        const int cc = (chunk & 1) << 7;
        const int kh = t / 3, kw = t - kh * 3;
        const int toffA = (kh * WP + kw) * CIN + cc;
        const int toffB = t * (COUT * CIN) + cc;
        const uint32_t stgA = sbase + stage * STG + dstb;
        const uint32_t stgB = stgA + A_BYTES;
#pragma unroll
        for (int k = 0; k < 4; k++)
            CP16(stgA + k * 4096, (const char*)g_xb + aoff[k] + toffA);
#pragma unroll
        for (int k = 0; k < 4; k++)
            CP16(stgB + k * 4096, (const char*)g_wb + boff[k] + toffB);
    };

    load_chunk(0, 0); CP_COMMIT();
    load_chunk(1, 1); CP_COMMIT();

    const int rowA0 = 32 * mw + rlo;
    const int rowB0 = 64 * nw + rlo;
    const uint32_t adr0 = rowA0 * 128;
    const uint32_t adr1 = (rowA0 + 16) * 128;

    int stage = 2;
    for (int i = 0; i < NCHUNK; i++) {
        CP_WAIT(1);
        __syncthreads();
        if (i + 2 < NCHUNK) load_chunk(i + 2, stage);
        CP_COMMIT();

        const int cur = (stage == 2) ? 0 : stage + 1;   // = i % 3
        stage = cur;
        const uint32_t stgA = sbase + cur * STG;
        const uint32_t stgB = stgA + A_BYTES;

        // ---- software-pipelined fragments: LDSM one step ahead of MMA ----
        uint32_t a_cur[2][4], a_nxt[2][4], bf_cur[4], bf_nxt[4];
        LDSM4(a_cur[0], stgA + adr0 + (khalf ^ swz));
        LDSM4(a_cur[1], stgA + adr1 + (khalf ^ swz));
        LDSM4(bf_cur,   stgB + rowB0 * 128 + (khalf ^ swz));
#pragma unroll
        for (int ks = 0; ks < 4; ks++) {
            const int kb  = ks * 32 + khalf;
            const int kbn = kb + 32;
#pragma unroll
            for (int nj = 0; nj < 4; nj++) {
                if (nj < 3) {
                    LDSM4(bf_nxt, stgB + (rowB0 + 16 * (nj + 1)) * 128 + (kb ^ swz));
                } else if (ks < 3) {
                    LDSM4(a_nxt[0], stgA + adr0 + (kbn ^ swz));
                    LDSM4(a_nxt[1], stgA + adr1 + (kbn ^ swz));
                    LDSM4(bf_nxt,   stgB + rowB0 * 128 + (kbn ^ swz));
                }
                MMAI(d[0][2 * nj],     a_cur[0], bf_cur[0], bf_cur[2]);
                MMAI(d[0][2 * nj + 1], a_cur[0], bf_cur[1], bf_cur[3]);
                MMAI(d[1][2 * nj],     a_cur[1], bf_cur[0], bf_cur[2]);
                MMAI(d[1][2 * nj + 1], a_cur[1], bf_cur[1], bf_cur[3]);
#pragma unroll
                for (int j = 0; j < 4; j++) bf_cur[j] = bf_nxt[j];
                if (nj == 3) {
#pragma unroll
                    for (int j = 0; j < 4; j++) {
                        a_cur[0][j] = a_nxt[0][j];
                        a_cur[1][j] = a_nxt[1][j];
                    }
                }
            }
        }
    }

    CP_WAIT(0);
    __syncthreads();

    // ---------------- epilogue (R7) ----------------
    int*  buf    = (int*)smem;                     // 64 cl x 128 rows = 32KB
    int*  stable = (int*)(smem + 40960);
    if (tid < 128) {
        int m = m0 + tid;
        int ib  = m / HW;
        int rem = m - ib * HW;
        stable[tid] = ib * (COUT * HW) + rem;
    }
    const int q  = lane & 3;
    const int rr = lane >> 2;
#pragma unroll 1
    for (int hh = 0; hh < 2; hh++) {
        if (nw == hh) {
#pragma unroll
            for (int mi = 0; mi < 2; mi++)
#pragma unroll
                for (int ni = 0; ni < 8; ni++) {
                    int cl  = 8 * ni + 2 * q;
                    int row = 32 * mw + 16 * mi + rr;
                    buf[cl * 128 + row]           = d[mi][ni][0];
                    buf[(cl + 1) * 128 + row]     = d[mi][ni][1];
                    buf[cl * 128 + row + 8]       = d[mi][ni][2];
                    buf[(cl + 1) * 128 + row + 8] = d[mi][ni][3];
                }
        }
        __syncthreads();
#pragma unroll 4
        for (int it = 0; it < 32; it++) {
            int u  = tid + 256 * it;
            int cl = u >> 7;
            int r  = u & 127;
            int co = co0 + hh * 64 + cl;
            out[stable[r] + co * HW] = (float)buf[cl * 128 + r] * __ldg(&g_sa[co]);
        }
        __syncthreads();
    }
}

// ---------------- launch ----------------
extern "C" void kernel_launch(void* const* d_in, const int* in_sizes, int n_in,
                              void* d_out, int out_size) {
    const float* x     = (const float*)d_in[0];  // [32,256,56,56]
    const float* wts   = (const float*)d_in[1];  // [4,256,256,3,3]
    const float* rv    = (const float*)d_in[2];  // [5]
    const float* alpha = (const float*)d_in[3];  // [256]
    float* out = (float*)d_out;

    cudaFuncSetAttribute(bconv_gemm, cudaFuncAttributeMaxDynamicSharedMemorySize, GSMEM);

    prep_all<<<COUT + 4 * H_ * B_, 256>>>(wts, rv, alpha, x);
    bconv_gemm<<<784 * 2, 256, GSMEM>>>(out);
}